// round 15
// baseline (speedup 1.0000x reference)
#include <cuda_runtime.h>

#define BATCH   8192
#define INS     64
#define OUTS    64
#define BTILE   8              // batch rows per block
#define NPAIR   4              // f32x2 pairs per thread (8 batch rows)
#define QSPLIT  4              // i-range split across warp groups
#define ICHUNK  (INS/QSPLIT)   // 16

// Packed f32x2 FMA (sm_103a FFMA2 — only reachable via PTX).
__device__ __forceinline__ float2 ffma2(float2 a, float2 b, float2 c) {
    float2 d;
    asm("{\n\t"
        ".reg .b64 ra, rb, rc, rd;\n\t"
        "mov.b64 ra, {%2, %3};\n\t"
        "mov.b64 rb, {%4, %5};\n\t"
        "mov.b64 rc, {%6, %7};\n\t"
        "fma.rn.f32x2 rd, ra, rb, rc;\n\t"
        "mov.b64 {%0, %1}, rd;\n\t"
        "}"
        : "=f"(d.x), "=f"(d.y)
        : "f"(a.x), "f"(a.y), "f"(b.x), "f"(b.y), "f"(c.x), "f"(c.y));
    return d;
}

__device__ __forceinline__ float2 relu2(float2 a) {
    a.x = fmaxf(a.x, 0.0f);
    a.y = fmaxf(a.y, 0.0f);
    return a;
}

__device__ __forceinline__ float2 bcast2(float v) { return make_float2(v, v); }

__global__ void __launch_bounds__(256, 5)
kan_kernel(const float* __restrict__ x,
           const float* __restrict__ w1, const float* __restrict__ b1,
           const float* __restrict__ w2, const float* __restrict__ b2,
           const float* __restrict__ w3, const float* __restrict__ b3,
           float* __restrict__ out)
{
    __shared__ float xs[INS * BTILE];                 // xs[i*8 + b]
    __shared__ float part[QSPLIT * BTILE * OUTS];     // part[q][b][o]

    const int tid = threadIdx.x;
    const int o   = tid & (OUTS - 1);     // 0..63
    const int q   = tid >> 6;             // 0..3 : i-range quarter
    const int b0  = blockIdx.x * BTILE;

    // Stage x tile transposed: xs[i][b]. Coalesced global reads.
    #pragma unroll
    for (int k = 0; k < (BTILE * INS) / 256; k++) {
        int idx = k * 256 + tid;
        int b = idx >> 6;
        int i = idx & (INS - 1);
        xs[i * BTILE + b] = x[(b0 + b) * INS + i];
    }
    __syncthreads();

    float2 acc[NPAIR];
    #pragma unroll
    for (int j = 0; j < NPAIR; j++) acc[j] = make_float2(0.0f, 0.0f);
    float sb3 = 0.0f;

    const float2* __restrict__ w1v = (const float2*)w1;
    const float2* __restrict__ b1v = (const float2*)b1;
    const float4* __restrict__ w2v = (const float4*)w2;
    const float2* __restrict__ b2v = (const float2*)b2;
    const float2* __restrict__ w3v = (const float2*)w3;

    const int i_lo = q * ICHUNK;

    // Software pipeline: params for iteration ii+1 load during compute of ii.
    int po = i_lo * OUTS + o;
    float2 nW1 = __ldg(w1v + po);
    float2 nB1 = __ldg(b1v + po);
    float4 nW2 = __ldg(w2v + po);
    float2 nB2 = __ldg(b2v + po);
    float2 nW3 = __ldg(w3v + po);
    float  nB3 = __ldg(b3  + po);

    #pragma unroll 4
    for (int ii = 0; ii < ICHUNK; ii++) {
        const float2 W1 = nW1, B1 = nB1, B2 = nB2, W3 = nW3;
        const float4 W2 = nW2;
        sb3 += nB3;

        // prefetch next (wraps on last iter — harmless redundant load)
        const int pn = (i_lo + ((ii + 1) & (ICHUNK - 1))) * OUTS + o;
        nW1 = __ldg(w1v + pn);
        nB1 = __ldg(b1v + pn);
        nW2 = __ldg(w2v + pn);
        nB2 = __ldg(b2v + pn);
        nW3 = __ldg(w3v + pn);
        nB3 = __ldg(b3  + pn);

        const float2 w1a = bcast2(W1.x), w1b = bcast2(W1.y);
        const float2 b1a = bcast2(B1.x), b1b = bcast2(B1.y);
        const float2 wA  = bcast2(W2.x), wB  = bcast2(W2.y);
        const float2 wC  = bcast2(W2.z), wD  = bcast2(W2.w);
        const float2 b2a = bcast2(B2.x), b2b = bcast2(B2.y);
        const float2 w3a = bcast2(W3.x), w3b = bcast2(W3.y);

        const float* xrow = &xs[(i_lo + ii) * BTILE];

        // 2x LDS.128 (warp-uniform broadcast, 32B-aligned) instead of 4x LDS.64
        const float4 xq0 = *(const float4*)(xrow);
        const float4 xq1 = *(const float4*)(xrow + 4);
        float2 xv[NPAIR];
        xv[0] = make_float2(xq0.x, xq0.y);
        xv[1] = make_float2(xq0.z, xq0.w);
        xv[2] = make_float2(xq1.x, xq1.y);
        xv[3] = make_float2(xq1.z, xq1.w);

        #pragma unroll
        for (int j = 0; j < NPAIR; j++) {
            float2 t0 = relu2(ffma2(xv[j], w1a, b1a));
            float2 t1 = relu2(ffma2(xv[j], w1b, b1b));
            float2 u0 = relu2(ffma2(t0, wA, ffma2(t1, wB, b2a)));
            float2 u1 = relu2(ffma2(t0, wC, ffma2(t1, wD, b2b)));
            acc[j] = ffma2(u0, w3a, ffma2(u1, w3b, acc[j]));
        }
    }

    // Fold this i-quarter's b3 sum into each batch element's partial.
    float* pq = &part[q * BTILE * OUTS];
    #pragma unroll
    for (int j = 0; j < NPAIR; j++) {
        pq[(2 * j)     * OUTS + o] = acc[j].x + sb3;
        pq[(2 * j + 1) * OUTS + o] = acc[j].y + sb3;
    }
    __syncthreads();

    // Reduce the four i-quarters; vectorized coalesced store.
    {
        const float2* p2 = (const float2*)part;
        float2 a = p2[tid];
        float2 b = p2[256 + tid];
        float2 c = p2[512 + tid];
        float2 d = p2[768 + tid];
        float2 r;
        r.x = (a.x + b.x) + (c.x + d.x);
        r.y = (a.y + b.y) + (c.y + d.y);
        *(float2*)&out[b0 * OUTS + 2 * tid] = r;
    }
}

extern "C" void kernel_launch(void* const* d_in, const int* in_sizes, int n_in,
                              void* d_out, int out_size)
{
    const float* x  = (const float*)d_in[0];
    const float* w1 = (const float*)d_in[1];
    const float* b1 = (const float*)d_in[2];
    const float* w2 = (const float*)d_in[3];
    const float* b2 = (const float*)d_in[4];
    const float* w3 = (const float*)d_in[5];
    const float* b3 = (const float*)d_in[6];
    float* out = (float*)d_out;

    kan_kernel<<<BATCH / BTILE, 256>>>(x, w1, b1, w2, b2, w3, b3, out);
}

// round 16
// speedup vs baseline: 1.1315x; 1.1315x over previous
#include <cuda_runtime.h>

#define BATCH   8192
#define INS     64
#define OUTS    64
#define BTILE   8              // batch rows per block
#define NPAIR   4              // f32x2 pairs per thread (8 batch rows)
#define QSPLIT  4              // i-range split across warp groups
#define ICHUNK  (INS/QSPLIT)   // 16

// Packed f32x2 FMA (sm_103a FFMA2 — only reachable via PTX).
__device__ __forceinline__ float2 ffma2(float2 a, float2 b, float2 c) {
    float2 d;
    asm("{\n\t"
        ".reg .b64 ra, rb, rc, rd;\n\t"
        "mov.b64 ra, {%2, %3};\n\t"
        "mov.b64 rb, {%4, %5};\n\t"
        "mov.b64 rc, {%6, %7};\n\t"
        "fma.rn.f32x2 rd, ra, rb, rc;\n\t"
        "mov.b64 {%0, %1}, rd;\n\t"
        "}"
        : "=f"(d.x), "=f"(d.y)
        : "f"(a.x), "f"(a.y), "f"(b.x), "f"(b.y), "f"(c.x), "f"(c.y));
    return d;
}

__device__ __forceinline__ float2 relu2(float2 a) {
    a.x = fmaxf(a.x, 0.0f);
    a.y = fmaxf(a.y, 0.0f);
    return a;
}

__device__ __forceinline__ float2 bcast2(float v) { return make_float2(v, v); }

__global__ void __launch_bounds__(256, 4)
kan_kernel(const float* __restrict__ x,
           const float* __restrict__ w1, const float* __restrict__ b1,
           const float* __restrict__ w2, const float* __restrict__ b2,
           const float* __restrict__ w3, const float* __restrict__ b3,
           float* __restrict__ out)
{
    __shared__ float xs[INS * BTILE];                 // xs[i*8 + b]
    __shared__ float part[QSPLIT * BTILE * OUTS];     // part[q][b][o]

    const int tid = threadIdx.x;
    const int o   = tid & (OUTS - 1);     // 0..63
    const int q   = tid >> 6;             // 0..3 : i-range quarter
    const int b0  = blockIdx.x * BTILE;

    // Stage x tile transposed: xs[i][b]. Coalesced global reads.
    #pragma unroll
    for (int k = 0; k < (BTILE * INS) / 256; k++) {
        int idx = k * 256 + tid;
        int b = idx >> 6;
        int i = idx & (INS - 1);
        xs[i * BTILE + b] = x[(b0 + b) * INS + i];
    }
    __syncthreads();

    float2 acc[NPAIR];
    #pragma unroll
    for (int j = 0; j < NPAIR; j++) acc[j] = make_float2(0.0f, 0.0f);
    float sb3 = 0.0f;

    const float2* __restrict__ w1v = (const float2*)w1;
    const float2* __restrict__ b1v = (const float2*)b1;
    const float4* __restrict__ w2v = (const float4*)w2;
    const float2* __restrict__ b2v = (const float2*)b2;
    const float2* __restrict__ w3v = (const float2*)w3;

    const int i_lo = q * ICHUNK;

    // Software pipeline: params for iteration ii+1 load during compute of ii.
    int po = i_lo * OUTS + o;
    float2 nW1 = __ldg(w1v + po);
    float2 nB1 = __ldg(b1v + po);
    float4 nW2 = __ldg(w2v + po);
    float2 nB2 = __ldg(b2v + po);
    float2 nW3 = __ldg(w3v + po);
    float  nB3 = __ldg(b3  + po);

    #pragma unroll 8
    for (int ii = 0; ii < ICHUNK; ii++) {
        const float2 W1 = nW1, B1 = nB1, B2 = nB2, W3 = nW3;
        const float4 W2 = nW2;
        sb3 += nB3;

        // prefetch next (wraps on last iter — harmless redundant load)
        const int pn = (i_lo + ((ii + 1) & (ICHUNK - 1))) * OUTS + o;
        nW1 = __ldg(w1v + pn);
        nB1 = __ldg(b1v + pn);
        nW2 = __ldg(w2v + pn);
        nB2 = __ldg(b2v + pn);
        nW3 = __ldg(w3v + pn);
        nB3 = __ldg(b3  + pn);

        const float2 w1a = bcast2(W1.x), w1b = bcast2(W1.y);
        const float2 b1a = bcast2(B1.x), b1b = bcast2(B1.y);
        const float2 wA  = bcast2(W2.x), wB  = bcast2(W2.y);
        const float2 wC  = bcast2(W2.z), wD  = bcast2(W2.w);
        const float2 b2a = bcast2(B2.x), b2b = bcast2(B2.y);
        const float2 w3a = bcast2(W3.x), w3b = bcast2(W3.y);

        const float* xrow = &xs[(i_lo + ii) * BTILE];

        // 2x LDS.128 (warp-uniform broadcast, 32B-aligned)
        const float4 xq0 = *(const float4*)(xrow);
        const float4 xq1 = *(const float4*)(xrow + 4);
        float2 xv[NPAIR];
        xv[0] = make_float2(xq0.x, xq0.y);
        xv[1] = make_float2(xq0.z, xq0.w);
        xv[2] = make_float2(xq1.x, xq1.y);
        xv[3] = make_float2(xq1.z, xq1.w);

        #pragma unroll
        for (int j = 0; j < NPAIR; j++) {
            float2 t0 = relu2(ffma2(xv[j], w1a, b1a));
            float2 t1 = relu2(ffma2(xv[j], w1b, b1b));
            float2 u0 = relu2(ffma2(t0, wA, ffma2(t1, wB, b2a)));
            float2 u1 = relu2(ffma2(t0, wC, ffma2(t1, wD, b2b)));
            acc[j] = ffma2(u0, w3a, ffma2(u1, w3b, acc[j]));
        }
    }

    // Fold this i-quarter's b3 sum into each batch element's partial.
    float* pq = &part[q * BTILE * OUTS];
    #pragma unroll
    for (int j = 0; j < NPAIR; j++) {
        pq[(2 * j)     * OUTS + o] = acc[j].x + sb3;
        pq[(2 * j + 1) * OUTS + o] = acc[j].y + sb3;
    }
    __syncthreads();

    // Reduce the four i-quarters; vectorized coalesced store.
    {
        const float2* p2 = (const float2*)part;
        float2 a = p2[tid];
        float2 b = p2[256 + tid];
        float2 c = p2[512 + tid];
        float2 d = p2[768 + tid];
        float2 r;
        r.x = (a.x + b.x) + (c.x + d.x);
        r.y = (a.y + b.y) + (c.y + d.y);
        *(float2*)&out[b0 * OUTS + 2 * tid] = r;
    }
}

extern "C" void kernel_launch(void* const* d_in, const int* in_sizes, int n_in,
                              void* d_out, int out_size)
{
    const float* x  = (const float*)d_in[0];
    const float* w1 = (const float*)d_in[1];
    const float* b1 = (const float*)d_in[2];
    const float* w2 = (const float*)d_in[3];
    const float* b2 = (const float*)d_in[4];
    const float* w3 = (const float*)d_in[5];
    const float* b3 = (const float*)d_in[6];
    float* out = (float*)d_out;

    kan_kernel<<<BATCH / BTILE, 256>>>(x, w1, b1, w2, b2, w3, b3, out);
}

// round 17
// speedup vs baseline: 1.1954x; 1.0565x over previous
#include <cuda_runtime.h>

#define BATCH   8192
#define INS     64
#define OUTS    64
#define BTILE   8              // batch rows per block
#define NPAIR   4              // f32x2 pairs per thread (8 batch rows)
#define QSPLIT  4              // i-range split across warp groups
#define ICHUNK  (INS/QSPLIT)   // 16

// Packed f32x2 FMA (sm_103a FFMA2 — only reachable via PTX).
__device__ __forceinline__ float2 ffma2(float2 a, float2 b, float2 c) {
    float2 d;
    asm("{\n\t"
        ".reg .b64 ra, rb, rc, rd;\n\t"
        "mov.b64 ra, {%2, %3};\n\t"
        "mov.b64 rb, {%4, %5};\n\t"
        "mov.b64 rc, {%6, %7};\n\t"
        "fma.rn.f32x2 rd, ra, rb, rc;\n\t"
        "mov.b64 {%0, %1}, rd;\n\t"
        "}"
        : "=f"(d.x), "=f"(d.y)
        : "f"(a.x), "f"(a.y), "f"(b.x), "f"(b.y), "f"(c.x), "f"(c.y));
    return d;
}

__device__ __forceinline__ float2 relu2(float2 a) {
    a.x = fmaxf(a.x, 0.0f);
    a.y = fmaxf(a.y, 0.0f);
    return a;
}

__device__ __forceinline__ float2 bcast2(float v) { return make_float2(v, v); }

__global__ void __launch_bounds__(256, 4)
kan_kernel(const float* __restrict__ x,
           const float* __restrict__ w1, const float* __restrict__ b1,
           const float* __restrict__ w2, const float* __restrict__ b2,
           const float* __restrict__ w3, const float* __restrict__ b3,
           float* __restrict__ out)
{
    __shared__ float xs[INS * BTILE];                 // xs[i*8 + b]
    __shared__ float part[QSPLIT * BTILE * OUTS];     // part[q][b][o]

    const int tid = threadIdx.x;
    const int o   = tid & (OUTS - 1);     // 0..63
    const int q   = tid >> 6;             // 0..3 : i-range quarter
    const int b0  = blockIdx.x * BTILE;

    // Stage x tile transposed: xs[i][b]. Coalesced global reads.
    #pragma unroll
    for (int k = 0; k < (BTILE * INS) / 256; k++) {
        int idx = k * 256 + tid;
        int b = idx >> 6;
        int i = idx & (INS - 1);
        xs[i * BTILE + b] = x[(b0 + b) * INS + i];
    }
    __syncthreads();

    float2 acc[NPAIR];
    #pragma unroll
    for (int j = 0; j < NPAIR; j++) acc[j] = make_float2(0.0f, 0.0f);
    float sb3 = 0.0f;

    const float2* __restrict__ w1v = (const float2*)w1;
    const float2* __restrict__ b1v = (const float2*)b1;
    const float4* __restrict__ w2v = (const float4*)w2;
    const float2* __restrict__ b2v = (const float2*)b2;
    const float2* __restrict__ w3v = (const float2*)w3;

    const int i_lo = q * ICHUNK;

    // Software pipeline: params for iteration ii+1 load during compute of ii.
    int po = i_lo * OUTS + o;
    float2 nW1 = __ldg(w1v + po);
    float2 nB1 = __ldg(b1v + po);
    float4 nW2 = __ldg(w2v + po);
    float2 nB2 = __ldg(b2v + po);
    float2 nW3 = __ldg(w3v + po);
    float  nB3 = __ldg(b3  + po);

    #pragma unroll 8
    for (int ii = 0; ii < ICHUNK; ii++) {
        const float2 W1 = nW1, B1 = nB1, B2 = nB2, W3 = nW3;
        const float4 W2 = nW2;
        sb3 += nB3;

        // prefetch next (wraps on last iter — harmless redundant load)
        const int pn = (i_lo + ((ii + 1) & (ICHUNK - 1))) * OUTS + o;
        nW1 = __ldg(w1v + pn);
        nB1 = __ldg(b1v + pn);
        nW2 = __ldg(w2v + pn);
        nB2 = __ldg(b2v + pn);
        nW3 = __ldg(w3v + pn);
        nB3 = __ldg(b3  + pn);

        const float2 w1a = bcast2(W1.x), w1b = bcast2(W1.y);
        const float2 b1a = bcast2(B1.x), b1b = bcast2(B1.y);
        const float2 wA  = bcast2(W2.x), wB  = bcast2(W2.y);
        const float2 wC  = bcast2(W2.z), wD  = bcast2(W2.w);
        const float2 b2a = bcast2(B2.x), b2b = bcast2(B2.y);
        const float2 w3a = bcast2(W3.x), w3b = bcast2(W3.y);

        const float* xrow = &xs[(i_lo + ii) * BTILE];

        // 2x LDS.128 (warp-uniform broadcast, 32B-aligned)
        const float4 xq0 = *(const float4*)(xrow);
        const float4 xq1 = *(const float4*)(xrow + 4);
        float2 xv[NPAIR];
        xv[0] = make_float2(xq0.x, xq0.y);
        xv[1] = make_float2(xq0.z, xq0.w);
        xv[2] = make_float2(xq1.x, xq1.y);
        xv[3] = make_float2(xq1.z, xq1.w);

        #pragma unroll
        for (int j = 0; j < NPAIR; j++) {
            float2 t0 = relu2(ffma2(xv[j], w1a, b1a));
            float2 t1 = relu2(ffma2(xv[j], w1b, b1b));
            float2 u0 = relu2(ffma2(t0, wA, ffma2(t1, wB, b2a)));
            float2 u1 = relu2(ffma2(t0, wC, ffma2(t1, wD, b2b)));
            acc[j] = ffma2(u0, w3a, ffma2(u1, w3b, acc[j]));
        }
    }

    // Fold this i-quarter's b3 sum into each batch element's partial.
    float* pq = &part[q * BTILE * OUTS];
    #pragma unroll
    for (int j = 0; j < NPAIR; j++) {
        pq[(2 * j)     * OUTS + o] = acc[j].x + sb3;
        pq[(2 * j + 1) * OUTS + o] = acc[j].y + sb3;
    }
    __syncthreads();

    // Reduce the four i-quarters; vectorized coalesced store.
    {
        const float2* p2 = (const float2*)part;
        float2 a = p2[tid];
        float2 b = p2[256 + tid];
        float2 c = p2[512 + tid];
        float2 d = p2[768 + tid];
        float2 r;
        r.x = (a.x + b.x) + (c.x + d.x);
        r.y = (a.y + b.y) + (c.y + d.y);
        *(float2*)&out[b0 * OUTS + 2 * tid] = r;
    }
}

extern "C" void kernel_launch(void* const* d_in, const int* in_sizes, int n_in,
                              void* d_out, int out_size)
{
    const float* x  = (const float*)d_in[0];
    const float* w1 = (const float*)d_in[1];
    const float* b1 = (const float*)d_in[2];
    const float* w2 = (const float*)d_in[3];
    const float* b2 = (const float*)d_in[4];
    const float* w3 = (const float*)d_in[5];
    const float* b3 = (const float*)d_in[6];
    float* out = (float*)d_out;

    kan_kernel<<<BATCH / BTILE, 256>>>(x, w1, b1, w2, b2, w3, b3, out);
}